// round 2
// baseline (speedup 1.0000x reference)
#include <cuda_runtime.h>
#include <cuda_bf16.h>
#include <math.h>

// ---------------- problem constants ----------------
#define BATCH   2
#define SEQLEN  2048
#define DMODEL  512
#define DSTATE  64
#define DCONV   4
#define NHEADS  16
#define HEADDIM 64
#define DINNER  1024                   // EXPAND * DMODEL
#define DIP     2192                   // 2*DINNER + 2*DSTATE + NHEADS
#define MROWS   (BATCH*SEQLEN)         // 4096

// ---------------- scratch (no cudaMalloc allowed) ----------------
__device__ float g_proj [(size_t)MROWS * DIP];     // ~36 MB
__device__ float g_xssm [(size_t)MROWS * DINNER];  // 16 MB
__device__ float g_dA   [(size_t)MROWS * NHEADS];
__device__ float g_y    [(size_t)MROWS * DINNER];  // gated scan output, 16 MB

// ============================================================
// SGEMM: C[M,N] = A[M,K] * B[N,K]^T   (A,B,C row-major, fp32)
// 128x128 block tile, BK=8, 256 threads, 8x8 microtile,
// global->register prefetch to hide load latency.
// M,K must be multiples of 128/8; N guarded.
// ============================================================
#define BM 128
#define BN 128
#define BKK 8

__global__ __launch_bounds__(256, 2)
void sgemm_nt(const float* __restrict__ A, const float* __restrict__ Bw,
              float* __restrict__ C, int M, int N, int K)
{
    __shared__ float As[BKK][BM + 4];
    __shared__ float Bs[BKK][BN + 4];

    const int tid = threadIdx.x;
    const int m0 = blockIdx.y * BM;
    const int n0 = blockIdx.x * BN;
    const int tx = tid & 15;           // 0..15
    const int ty = tid >> 4;           // 0..15

    // loader mapping: each thread one float4 of A tile and one of B tile
    const int arow = tid >> 1;         // 0..127
    const int acol = (tid & 1) * 4;    // 0 or 4
    const float* Aptr = A + (size_t)(m0 + arow) * K + acol;
    const int  brow = arow;
    const int  bcol = acol;
    const bool bvalid = (n0 + brow) < N;
    const float* Bptr = Bw + (size_t)(n0 + brow) * K + bcol;

    float4 ra = *(const float4*)Aptr;
    float4 rb = bvalid ? *(const float4*)Bptr : make_float4(0.f,0.f,0.f,0.f);

    float c[8][8];
    #pragma unroll
    for (int i = 0; i < 8; i++)
        #pragma unroll
        for (int j = 0; j < 8; j++) c[i][j] = 0.f;

    const int nk = K / BKK;
    for (int kt = 0; kt < nk; kt++) {
        As[acol+0][arow] = ra.x; As[acol+1][arow] = ra.y;
        As[acol+2][arow] = ra.z; As[acol+3][arow] = ra.w;
        Bs[bcol+0][brow] = rb.x; Bs[bcol+1][brow] = rb.y;
        Bs[bcol+2][brow] = rb.z; Bs[bcol+3][brow] = rb.w;
        __syncthreads();

        if (kt + 1 < nk) {
            ra = *(const float4*)(Aptr + (size_t)(kt+1)*BKK);
            rb = bvalid ? *(const float4*)(Bptr + (size_t)(kt+1)*BKK)
                        : make_float4(0.f,0.f,0.f,0.f);
        }

        #pragma unroll
        for (int k = 0; k < BKK; k++) {
            float a[8], bv[8];
            *(float4*)&a[0]  = *(const float4*)&As[k][ty*8];
            *(float4*)&a[4]  = *(const float4*)&As[k][ty*8+4];
            *(float4*)&bv[0] = *(const float4*)&Bs[k][tx*8];
            *(float4*)&bv[4] = *(const float4*)&Bs[k][tx*8+4];
            #pragma unroll
            for (int i = 0; i < 8; i++)
                #pragma unroll
                for (int j = 0; j < 8; j++)
                    c[i][j] = fmaf(a[i], bv[j], c[i][j]);
        }
        __syncthreads();
    }

    // epilogue (N is a multiple of 16, so float4 columns are all-in or all-out)
    #pragma unroll
    for (int i = 0; i < 8; i++) {
        const int m = m0 + ty*8 + i;
        float* crow = C + (size_t)m * N;
        #pragma unroll
        for (int j4 = 0; j4 < 8; j4 += 4) {
            const int n = n0 + tx*8 + j4;
            if (n < N)
                *(float4*)&crow[n] = make_float4(c[i][j4], c[i][j4+1], c[i][j4+2], c[i][j4+3]);
        }
    }
}

// ============================================================
// depthwise causal conv1d (width 4) + bias + SiLU  ->  g_xssm
// ============================================================
__global__ void conv_silu_kernel(const float* __restrict__ cw,
                                 const float* __restrict__ cb)
{
    int idx = blockIdx.x * blockDim.x + threadIdx.x;
    if (idx >= BATCH * SEQLEN * DINNER) return;
    const int c = idx % DINNER;
    const int t = (idx / DINNER) % SEQLEN;
    const int b = idx / (DINNER * SEQLEN);

    const float* base = g_proj + (size_t)b * SEQLEN * DIP + DINNER + c; // xs slice
    float acc = cb[c];
    #pragma unroll
    for (int j = 0; j < DCONV; j++) {
        const int ts = t - (DCONV - 1) + j;
        if (ts >= 0) acc = fmaf(cw[c*DCONV + j], base[(size_t)ts * DIP], acc);
    }
    // SiLU
    const float sv = acc / (1.f + expf(-acc));
    g_xssm[idx] = sv;
}

// ============================================================
// dt path: dA = exp(softplus(dt_raw + dt_bias) * (-exp(A_log)))
// ============================================================
__global__ void dt_kernel(const float* __restrict__ A_log,
                          const float* __restrict__ dt_bias)
{
    int idx = blockIdx.x * blockDim.x + threadIdx.x;
    if (idx >= BATCH * SEQLEN * NHEADS) return;
    const int h = idx % NHEADS;
    const int row = idx / NHEADS;              // b*SEQLEN + t

    float dtr = g_proj[(size_t)row * DIP + 2*DINNER + 2*DSTATE + h] + dt_bias[h];
    float sp = (dtr > 20.f) ? dtr : log1pf(expf(dtr));
    float Aneg = -expf(A_log[h]);
    g_dA[idx] = expf(sp * Aneg);
}

// ============================================================
// Selective scan (+ z-gate), fp32, state in registers.
// grid: (4 p-quarters, NHEADS, BATCH), 128 threads (4 warps).
// Thread layout in warp: lane = ng*4 + pi  (pi in [0,4), ng in [0,8))
//   thread owns p = pg*16 + w*4 + pi, n in [ng*8, ng*8+8), state s[8].
// Per 64-step chunk: stage B/C/x/z/dA into shared.
// Per step: s[j] = dA*s[j] + B[n]*x[p];  y[p] += C[n]*s[j]; reduce over ng
// via shfl.bfly (xor 4,8,16), batched 8 steps to hide shuffle latency.
// ============================================================
__global__ __launch_bounds__(128, 1)
void scan_kernel()
{
    const int pg = blockIdx.x;       // 0..3
    const int h  = blockIdx.y;       // 0..15
    const int b  = blockIdx.z;       // 0..1

    const int tid  = threadIdx.x;
    const int lane = tid & 31;
    const int w    = tid >> 5;       // warp 0..3
    const int pi   = lane & 3;
    const int ng   = lane >> 2;      // 0..7
    const int p_local = w*4 + pi;    // 0..15
    const int n0   = ng * 8;

    __shared__ float sB [64][64];
    __shared__ float sC [64][64];
    __shared__ float sX [64][16];
    __shared__ float sZ [64][16];
    __shared__ float sDA[64];

    float s[8];
    #pragma unroll
    for (int j = 0; j < 8; j++) s[j] = 0.f;

    const size_t rowbase = (size_t)b * SEQLEN;
    const int pcol = h*64 + pg*16;   // base column into DINNER-wide tensors

    for (int tc = 0; tc < SEQLEN; tc += 64) {
        __syncthreads();   // protect shared from previous chunk's readers
        // --- stage B, C (64 rows x 64 floats each) ---
        for (int u = tid; u < 64*16; u += 128) {
            const int r  = u >> 4;
            const int c4 = (u & 15) * 4;
            const float* src = g_proj + (rowbase + tc + r) * (size_t)DIP;
            *(float4*)&sB[r][c4] = *(const float4*)(src + 2*DINNER + c4);
            *(float4*)&sC[r][c4] = *(const float4*)(src + 2*DINNER + DSTATE + c4);
        }
        // --- stage x (scan input) and z (gate), 64 x 16 each ---
        for (int u = tid; u < 64*4; u += 128) {
            const int r  = u >> 2;
            const int c4 = (u & 3) * 4;
            *(float4*)&sX[r][c4] =
                *(const float4*)(g_xssm + (rowbase + tc + r) * (size_t)DINNER + pcol + c4);
            *(float4*)&sZ[r][c4] =
                *(const float4*)(g_proj + (rowbase + tc + r) * (size_t)DIP + pcol + c4);
        }
        if (tid < 64) sDA[tid] = g_dA[(rowbase + tc + tid) * NHEADS + h];
        __syncthreads();

        #pragma unroll 1
        for (int g = 0; g < 64; g += 8) {
            float acc[8];
            #pragma unroll
            for (int q = 0; q < 8; q++) {
                const int tt = g + q;
                const float da = sDA[tt];
                const float xv = sX[tt][p_local];
                float4 b0 = *(const float4*)&sB[tt][n0];
                float4 b1 = *(const float4*)&sB[tt][n0+4];
                float4 c0 = *(const float4*)&sC[tt][n0];
                float4 c1 = *(const float4*)&sC[tt][n0+4];
                s[0] = fmaf(da, s[0], b0.x * xv);
                s[1] = fmaf(da, s[1], b0.y * xv);
                s[2] = fmaf(da, s[2], b0.z * xv);
                s[3] = fmaf(da, s[3], b0.w * xv);
                s[4] = fmaf(da, s[4], b1.x * xv);
                s[5] = fmaf(da, s[5], b1.y * xv);
                s[6] = fmaf(da, s[6], b1.z * xv);
                s[7] = fmaf(da, s[7], b1.w * xv);
                float a0 = c0.x * s[0];
                float a1 = c0.y * s[1];
                a0 = fmaf(c0.z, s[2], a0);
                a1 = fmaf(c0.w, s[3], a1);
                a0 = fmaf(c1.x, s[4], a0);
                a1 = fmaf(c1.y, s[5], a1);
                a0 = fmaf(c1.z, s[6], a0);
                a1 = fmaf(c1.w, s[7], a1);
                acc[q] = a0 + a1;
            }
            // reduce the 8 partial sums over the 8 n-groups (lanes xor 4,8,16)
            #pragma unroll
            for (int q = 0; q < 8; q++) {
                float a = acc[q];
                a += __shfl_xor_sync(0xffffffffu, a, 4);
                a += __shfl_xor_sync(0xffffffffu, a, 8);
                a += __shfl_xor_sync(0xffffffffu, a, 16);
                acc[q] = a;
            }
            if (ng == 0) {
                #pragma unroll
                for (int q = 0; q < 8; q++) {
                    const int tt = g + q;
                    const float zv = sZ[tt][p_local];
                    const float gate = zv / (1.f + expf(-zv));   // silu(z)
                    g_y[(rowbase + tc + tt) * (size_t)DINNER + pcol + p_local]
                        = acc[q] * gate;
                }
            }
        }
    }
}

// ============================================================
// launch
// ============================================================
extern "C" void kernel_launch(void* const* d_in, const int* in_sizes, int n_in,
                              void* d_out, int out_size)
{
    const float* x       = (const float*)d_in[0];   // [2,2048,512]
    const float* W_in    = (const float*)d_in[1];   // [2192,512]
    const float* conv_w  = (const float*)d_in[2];   // [1024,1,4]
    const float* conv_b  = (const float*)d_in[3];   // [1024]
    const float* A_log   = (const float*)d_in[4];   // [16]
    const float* dt_bias = (const float*)d_in[5];   // [16]
    const float* W_out   = (const float*)d_in[6];   // [512,1024]
    float* out = (float*)d_out;                     // [2,2048,512]

    float* proj; cudaGetSymbolAddress((void**)&proj, g_proj);
    float* yg;   cudaGetSymbolAddress((void**)&yg,   g_y);

    // 1) in_proj: proj = x @ W_in^T   (M=4096, N=2192, K=512)
    {
        dim3 grid((DIP + BN - 1)/BN, MROWS/BM);
        sgemm_nt<<<grid, 256>>>(x, W_in, proj, MROWS, DIP, DMODEL);
    }
    // 2) conv + silu
    {
        int total = BATCH*SEQLEN*DINNER;
        conv_silu_kernel<<<(total + 255)/256, 256>>>(conv_w, conv_b);
    }
    // 3) dt -> dA
    {
        int total = BATCH*SEQLEN*NHEADS;
        dt_kernel<<<(total + 255)/256, 256>>>(A_log, dt_bias);
    }
    // 4) selective scan + gate
    {
        dim3 grid(4, NHEADS, BATCH);
        scan_kernel<<<grid, 128>>>();
    }
    // 5) out_proj: out = y @ W_out^T  (M=4096, N=512, K=1024)
    {
        dim3 grid((DMODEL + BN - 1)/BN, MROWS/BM);
        sgemm_nt<<<grid, 256>>>(yg, W_out, out, MROWS, DMODEL, DINNER);
    }
}

// round 4
// speedup vs baseline: 1.3009x; 1.3009x over previous
#include <cuda_runtime.h>
#include <cuda_bf16.h>
#include <math.h>

// ---------------- problem constants ----------------
#define BATCH   2
#define SEQLEN  2048
#define DMODEL  512
#define DSTATE  64
#define DCONV   4
#define NHEADS  16
#define HEADDIM 64
#define DINNER  1024
#define DIP     2192                   // 2*DINNER + 2*DSTATE + NHEADS
#define MROWS   (BATCH*SEQLEN)         // 4096
#define CHUNK   64
#define NCHUNK  (SEQLEN/CHUNK)         // 32
#define NCI     (BATCH*NHEADS*NCHUNK)  // 1024 chunk instances

// ---------------- scratch ----------------
__device__ float g_proj  [(size_t)MROWS * DIP];      // ~36 MB
__device__ float g_xssm  [(size_t)MROWS * DINNER];   // 16 MB
__device__ float g_dA    [(size_t)MROWS * NHEADS];
__device__ float g_y     [(size_t)MROWS * DINNER];   // partial then final y
__device__ float g_P     [(size_t)NCI * CHUNK];      // inclusive cumprod per chunk
__device__ float g_vend  [(size_t)NCI * DSTATE * HEADDIM];   // 16.8 MB
__device__ float g_hstart[(size_t)NCI * DSTATE * HEADDIM];   // 16.8 MB

// ============================================================
// SGEMM: C[M,N] = A[M,K] * B[N,K]^T  (row-major fp32)
// ============================================================
#define BM 128
#define BN 128
#define BKK 8

__global__ __launch_bounds__(256, 2)
void sgemm_nt(const float* __restrict__ A, const float* __restrict__ Bw,
              float* __restrict__ C, int M, int N, int K)
{
    __shared__ float As[BKK][BM + 4];
    __shared__ float Bs[BKK][BN + 4];

    const int tid = threadIdx.x;
    const int m0 = blockIdx.y * BM;
    const int n0 = blockIdx.x * BN;
    const int tx = tid & 15;
    const int ty = tid >> 4;

    const int arow = tid >> 1;
    const int acol = (tid & 1) * 4;
    const float* Aptr = A + (size_t)(m0 + arow) * K + acol;
    const int  brow = arow;
    const int  bcol = acol;
    const bool bvalid = (n0 + brow) < N;
    const float* Bptr = Bw + (size_t)(n0 + brow) * K + bcol;

    float4 ra = *(const float4*)Aptr;
    float4 rb = bvalid ? *(const float4*)Bptr : make_float4(0.f,0.f,0.f,0.f);

    float c[8][8];
    #pragma unroll
    for (int i = 0; i < 8; i++)
        #pragma unroll
        for (int j = 0; j < 8; j++) c[i][j] = 0.f;

    const int nk = K / BKK;
    for (int kt = 0; kt < nk; kt++) {
        As[acol+0][arow] = ra.x; As[acol+1][arow] = ra.y;
        As[acol+2][arow] = ra.z; As[acol+3][arow] = ra.w;
        Bs[bcol+0][brow] = rb.x; Bs[bcol+1][brow] = rb.y;
        Bs[bcol+2][brow] = rb.z; Bs[bcol+3][brow] = rb.w;
        __syncthreads();

        if (kt + 1 < nk) {
            ra = *(const float4*)(Aptr + (size_t)(kt+1)*BKK);
            rb = bvalid ? *(const float4*)(Bptr + (size_t)(kt+1)*BKK)
                        : make_float4(0.f,0.f,0.f,0.f);
        }

        #pragma unroll
        for (int k = 0; k < BKK; k++) {
            float a[8], bv[8];
            *(float4*)&a[0]  = *(const float4*)&As[k][ty*8];
            *(float4*)&a[4]  = *(const float4*)&As[k][ty*8+4];
            *(float4*)&bv[0] = *(const float4*)&Bs[k][tx*8];
            *(float4*)&bv[4] = *(const float4*)&Bs[k][tx*8+4];
            #pragma unroll
            for (int i = 0; i < 8; i++)
                #pragma unroll
                for (int j = 0; j < 8; j++)
                    c[i][j] = fmaf(a[i], bv[j], c[i][j]);
        }
        __syncthreads();
    }

    #pragma unroll
    for (int i = 0; i < 8; i++) {
        const int m = m0 + ty*8 + i;
        float* crow = C + (size_t)m * N;
        #pragma unroll
        for (int j4 = 0; j4 < 8; j4 += 4) {
            const int n = n0 + tx*8 + j4;
            if (n < N)
                *(float4*)&crow[n] = make_float4(c[i][j4], c[i][j4+1], c[i][j4+2], c[i][j4+3]);
        }
    }
}

// ============================================================
// depthwise causal conv1d + bias + SiLU -> g_xssm
// ============================================================
__global__ void conv_silu_kernel(const float* __restrict__ cw,
                                 const float* __restrict__ cb)
{
    int idx = blockIdx.x * blockDim.x + threadIdx.x;
    if (idx >= BATCH * SEQLEN * DINNER) return;
    const int c = idx % DINNER;
    const int t = (idx / DINNER) % SEQLEN;
    const int b = idx / (DINNER * SEQLEN);

    const float* base = g_proj + (size_t)b * SEQLEN * DIP + DINNER + c;
    float acc = cb[c];
    #pragma unroll
    for (int j = 0; j < DCONV; j++) {
        const int ts = t - (DCONV - 1) + j;
        if (ts >= 0) acc = fmaf(cw[c*DCONV + j], base[(size_t)ts * DIP], acc);
    }
    const float sv = acc / (1.f + expf(-acc));
    g_xssm[idx] = sv;
}

// ============================================================
// dt path: dA = exp(softplus(dt_raw + dt_bias) * (-exp(A_log)))
// ============================================================
__global__ void dt_kernel(const float* __restrict__ A_log,
                          const float* __restrict__ dt_bias)
{
    int idx = blockIdx.x * blockDim.x + threadIdx.x;
    if (idx >= BATCH * SEQLEN * NHEADS) return;
    const int h = idx % NHEADS;
    const int row = idx / NHEADS;

    float dtr = g_proj[(size_t)row * DIP + 2*DINNER + 2*DSTATE + h] + dt_bias[h];
    float sp = (dtr > 20.f) ? dtr : log1pf(expf(dtr));
    float Aneg = -expf(A_log[h]);
    g_dA[idx] = expf(sp * Aneg);
}

// ============================================================
// Phase A: per-chunk local scan (zero init). Produces:
//   g_y     : partial y (C_t · v_t), ungated
//   g_vend  : local end state v_63  [n=64][p=64]
//   g_P     : inclusive cumprod of dA within chunk
// grid (4 pg, NHEADS, BATCH*NCHUNK), 128 threads.
// ============================================================
__global__ __launch_bounds__(128, 1)
void scan_chunk_kernel()
{
    const int pg = blockIdx.x;            // 0..3
    const int h  = blockIdx.y;            // 0..15
    const int bz = blockIdx.z;            // 0..63
    const int b  = bz >> 5;
    const int c  = bz & 31;

    const int tid  = threadIdx.x;
    const int lane = tid & 31;
    const int w    = tid >> 5;
    const int pi   = lane & 3;
    const int ng   = lane >> 2;           // 0..7
    const int p_local = w*4 + pi;         // 0..15
    const int n0   = ng * 8;

    __shared__ float sB [64][64];
    __shared__ float sC [64][64];
    __shared__ float sX [64][16];
    __shared__ float sDA[64];
    __shared__ float sP [64];

    const size_t rowbase = (size_t)b * SEQLEN + (size_t)c * CHUNK;
    const int pcol = h*64 + pg*16;
    const size_t ci = ((size_t)(b*NHEADS + h) * NCHUNK + c);

    // stage B, C
    for (int u = tid; u < 64*16; u += 128) {
        const int r  = u >> 4;
        const int c4 = (u & 15) * 4;
        const float* src = g_proj + (rowbase + r) * (size_t)DIP;
        *(float4*)&sB[r][c4] = *(const float4*)(src + 2*DINNER + c4);
        *(float4*)&sC[r][c4] = *(const float4*)(src + 2*DINNER + DSTATE + c4);
    }
    // stage x
    for (int u = tid; u < 64*4; u += 128) {
        const int r  = u >> 2;
        const int c4 = (u & 3) * 4;
        *(float4*)&sX[r][c4] =
            *(const float4*)(g_xssm + (rowbase + r) * (size_t)DINNER + pcol + c4);
    }
    if (tid < 64) {
        float v = g_dA[(rowbase + tid) * NHEADS + h];
        sDA[tid] = v;
        sP[tid]  = v;
    }
    __syncthreads();

    // inclusive cumprod of dA (Hillis-Steele), 6 steps
    #pragma unroll
    for (int off = 1; off < 64; off <<= 1) {
        float v = 0.f;
        if (tid < 64) {
            v = sP[tid];
            if (tid >= off) v *= sP[tid - off];
        }
        __syncthreads();
        if (tid < 64) sP[tid] = v;
        __syncthreads();
    }
    if (tid < 64 && pg == 0)  // one pg writes P (identical across pg)
        g_P[ci*CHUNK + tid] = sP[tid];

    float s[8];
    #pragma unroll
    for (int j = 0; j < 8; j++) s[j] = 0.f;

    #pragma unroll 1
    for (int g = 0; g < 64; g += 8) {
        float acc[8];
        #pragma unroll
        for (int q = 0; q < 8; q++) {
            const int tt = g + q;
            const float da = sDA[tt];
            const float xv = sX[tt][p_local];
            float4 b0 = *(const float4*)&sB[tt][n0];
            float4 b1 = *(const float4*)&sB[tt][n0+4];
            float4 c0 = *(const float4*)&sC[tt][n0];
            float4 c1 = *(const float4*)&sC[tt][n0+4];
            s[0] = fmaf(da, s[0], b0.x * xv);
            s[1] = fmaf(da, s[1], b0.y * xv);
            s[2] = fmaf(da, s[2], b0.z * xv);
            s[3] = fmaf(da, s[3], b0.w * xv);
            s[4] = fmaf(da, s[4], b1.x * xv);
            s[5] = fmaf(da, s[5], b1.y * xv);
            s[6] = fmaf(da, s[6], b1.z * xv);
            s[7] = fmaf(da, s[7], b1.w * xv);
            float a0 = c0.x * s[0];
            float a1 = c0.y * s[1];
            a0 = fmaf(c0.z, s[2], a0);
            a1 = fmaf(c0.w, s[3], a1);
            a0 = fmaf(c1.x, s[4], a0);
            a1 = fmaf(c1.y, s[5], a1);
            a0 = fmaf(c1.z, s[6], a0);
            a1 = fmaf(c1.w, s[7], a1);
            acc[q] = a0 + a1;
        }
        #pragma unroll
        for (int q = 0; q < 8; q++) {
            float a = acc[q];
            a += __shfl_xor_sync(0xffffffffu, a, 4);
            a += __shfl_xor_sync(0xffffffffu, a, 8);
            a += __shfl_xor_sync(0xffffffffu, a, 16);
            acc[q] = a;
        }
        if (ng == 0) {
            #pragma unroll
            for (int q = 0; q < 8; q++) {
                g_y[(rowbase + g + q) * (size_t)DINNER + pcol + p_local] = acc[q];
            }
        }
    }

    // write local end-state v_63: layout [ci][n][p]
    float* vend = g_vend + ci * (size_t)(DSTATE*HEADDIM);
    #pragma unroll
    for (int j = 0; j < 8; j++)
        vend[(n0 + j) * HEADDIM + pg*16 + p_local] = s[j];
}

// ============================================================
// Phase B: carry propagation across chunks (sequential, tiny).
// grid 32 (b*h), 256 threads, state in registers.
// g_hstart[ci] = carry-in state for chunk c.
// ============================================================
__global__ __launch_bounds__(256, 1)
void carry_kernel()
{
    const int bh  = blockIdx.x;           // 0..31
    const int tid = threadIdx.x;

    float hreg[16];
    #pragma unroll
    for (int k = 0; k < 16; k++) hreg[k] = 0.f;

    for (int c = 0; c < NCHUNK; c++) {
        const size_t ci = (size_t)bh * NCHUNK + c;
        const float Pend = g_P[ci*CHUNK + (CHUNK-1)];
        float*       hs = g_hstart + ci * (size_t)(DSTATE*HEADDIM);
        const float* ve = g_vend   + ci * (size_t)(DSTATE*HEADDIM);
        #pragma unroll
        for (int k = 0; k < 16; k++) {
            const int cell = tid + k*256;
            hs[cell] = hreg[k];
            hreg[k] = fmaf(Pend, hreg[k], ve[cell]);
        }
    }
}

// ============================================================
// Phase C: correction + gate.
//   y_t = (y_partial_t + P_t * (C_t · hstart)) * silu(z_t)
// grid NCI=1024, 256 threads; 64x64x64 mini-GEMM in shared.
// ============================================================
__global__ __launch_bounds__(256, 4)
void correct_gate_kernel()
{
    const int ci = blockIdx.x;            // 0..1023
    const int c  = ci & 31;
    const int bh = ci >> 5;
    const int h  = bh & 15;
    const int b  = bh >> 4;
    const int tid = threadIdx.x;

    __shared__ float sCt[64][72];   // C transposed: [n][t]
    __shared__ float sHS[64][64];   // hstart [n][p]
    __shared__ float sPc[64];

    const size_t rowbase = (size_t)b * SEQLEN + (size_t)c * CHUNK;

    // stage C (transpose) and hstart
    for (int u = tid; u < 64*16; u += 256) {
        const int r  = u >> 4;
        const int c4 = (u & 15) * 4;
        float4 v = *(const float4*)(g_proj + (rowbase + r) * (size_t)DIP
                                    + 2*DINNER + DSTATE + c4);
        sCt[c4+0][r] = v.x; sCt[c4+1][r] = v.y;
        sCt[c4+2][r] = v.z; sCt[c4+3][r] = v.w;
    }
    const float* hs = g_hstart + (size_t)ci * (DSTATE*HEADDIM);
    for (int u = tid; u < 64*16; u += 256) {
        const int r  = u >> 4;
        const int c4 = (u & 15) * 4;
        *(float4*)&sHS[r][c4] = *(const float4*)(hs + r*HEADDIM + c4);
    }
    if (tid < 64) sPc[tid] = g_P[(size_t)ci*CHUNK + tid];
    __syncthreads();

    const int tx = tid & 15;              // p block
    const int ty = tid >> 4;              // t block
    const int t0 = ty * 4;
    const int p0 = tx * 4;

    float acc[4][4];
    #pragma unroll
    for (int i = 0; i < 4; i++)
        #pragma unroll
        for (int j = 0; j < 4; j++) acc[i][j] = 0.f;

    #pragma unroll 4
    for (int n = 0; n < 64; n++) {
        float4 cv = *(const float4*)&sCt[n][t0];
        float4 hv = *(const float4*)&sHS[n][p0];
        float ct[4] = {cv.x, cv.y, cv.z, cv.w};
        float hh[4] = {hv.x, hv.y, hv.z, hv.w};
        #pragma unroll
        for (int i = 0; i < 4; i++)
            #pragma unroll
            for (int j = 0; j < 4; j++)
                acc[i][j] = fmaf(ct[i], hh[j], acc[i][j]);
    }

    #pragma unroll
    for (int i = 0; i < 4; i++) {
        const size_t row = rowbase + t0 + i;
        const float P = sPc[t0 + i];
        float4 yp = *(const float4*)(g_y + row * (size_t)DINNER + h*64 + p0);
        float4 zv = *(const float4*)(g_proj + row * (size_t)DIP + h*64 + p0);
        float4 o;
        float g0 = zv.x / (1.f + expf(-zv.x));
        float g1 = zv.y / (1.f + expf(-zv.y));
        float g2 = zv.z / (1.f + expf(-zv.z));
        float g3 = zv.w / (1.f + expf(-zv.w));
        o.x = (yp.x + P*acc[i][0]) * g0;
        o.y = (yp.y + P*acc[i][1]) * g1;
        o.z = (yp.z + P*acc[i][2]) * g2;
        o.w = (yp.w + P*acc[i][3]) * g3;
        *(float4*)(g_y + row * (size_t)DINNER + h*64 + p0) = o;
    }
}

// ============================================================
// launch
// ============================================================
extern "C" void kernel_launch(void* const* d_in, const int* in_sizes, int n_in,
                              void* d_out, int out_size)
{
    const float* x       = (const float*)d_in[0];
    const float* W_in    = (const float*)d_in[1];
    const float* conv_w  = (const float*)d_in[2];
    const float* conv_b  = (const float*)d_in[3];
    const float* A_log   = (const float*)d_in[4];
    const float* dt_bias = (const float*)d_in[5];
    const float* W_out   = (const float*)d_in[6];
    float* out = (float*)d_out;

    float* proj; cudaGetSymbolAddress((void**)&proj, g_proj);
    float* yg;   cudaGetSymbolAddress((void**)&yg,   g_y);

    // 1) in_proj: proj = x @ W_in^T
    {
        dim3 grid((DIP + BN - 1)/BN, MROWS/BM);
        sgemm_nt<<<grid, 256>>>(x, W_in, proj, MROWS, DIP, DMODEL);
    }
    // 2) conv + silu
    {
        int total = BATCH*SEQLEN*DINNER;
        conv_silu_kernel<<<(total + 255)/256, 256>>>(conv_w, conv_b);
    }
    // 3) dt -> dA
    {
        int total = BATCH*SEQLEN*NHEADS;
        dt_kernel<<<(total + 255)/256, 256>>>(A_log, dt_bias);
    }
    // 4a) per-chunk local scan
    {
        dim3 grid(4, NHEADS, BATCH*NCHUNK);
        scan_chunk_kernel<<<grid, 128>>>();
    }
    // 4b) carry propagation
    carry_kernel<<<BATCH*NHEADS, 256>>>();
    // 4c) correction + gate
    correct_gate_kernel<<<NCI, 256>>>();
    // 5) out_proj
    {
        dim3 grid((DMODEL + BN - 1)/BN, MROWS/BM);
        sgemm_nt<<<grid, 256>>>(yg, W_out, out, MROWS, DMODEL, DINNER);
    }
}

// round 7
// speedup vs baseline: 2.2215x; 1.7077x over previous
#include <cuda_runtime.h>
#include <cuda_bf16.h>
#include <math.h>
#include <stdint.h>

// ---------------- problem constants ----------------
#define BATCH   2
#define SEQLEN  2048
#define DMODEL  512
#define DSTATE  64
#define DCONV   4
#define NHEADS  16
#define HEADDIM 64
#define DINNER  1024
#define DIP     2192                   // 2*DINNER + 2*DSTATE + NHEADS
#define MROWS   (BATCH*SEQLEN)         // 4096
#define CHUNK   64
#define NCHUNK  (SEQLEN/CHUNK)         // 32
#define NCI     (BATCH*NHEADS*NCHUNK)  // 1024 chunk instances

// ---------------- scratch ----------------
__device__ float g_proj  [(size_t)MROWS * DIP];
__device__ float g_xssm  [(size_t)MROWS * DINNER];
__device__ float g_dA    [(size_t)MROWS * NHEADS];
__device__ float g_y     [(size_t)MROWS * DINNER];
__device__ float g_P     [(size_t)NCI * CHUNK];
__device__ float g_vend  [(size_t)NCI * DSTATE * HEADDIM];
__device__ float g_hstart[(size_t)NCI * DSTATE * HEADDIM];

// bf16 split tensors
__device__ __nv_bfloat16 g_xhi [(size_t)MROWS * DMODEL];
__device__ __nv_bfloat16 g_xlo [(size_t)MROWS * DMODEL];
__device__ __nv_bfloat16 g_wihi[(size_t)DIP * DMODEL];
__device__ __nv_bfloat16 g_wilo[(size_t)DIP * DMODEL];
__device__ __nv_bfloat16 g_wohi[(size_t)DMODEL * DINNER];
__device__ __nv_bfloat16 g_wolo[(size_t)DMODEL * DINNER];
__device__ __nv_bfloat16 g_yhi [(size_t)MROWS * DINNER];
__device__ __nv_bfloat16 g_ylo [(size_t)MROWS * DINNER];

// ================= helpers =================
__device__ __forceinline__ uint32_t smem_u32(const void* p) {
    uint32_t a;
    asm("{ .reg .u64 t; cvta.to.shared.u64 t, %1; cvt.u32.u64 %0, t; }"
        : "=r"(a) : "l"(p));
    return a;
}

#define LDSM4(r, addr) \
    asm volatile("ldmatrix.sync.aligned.m8n8.x4.shared.b16 {%0,%1,%2,%3}, [%4];" \
        : "=r"((r)[0]), "=r"((r)[1]), "=r"((r)[2]), "=r"((r)[3]) : "r"(addr))
#define LDSM2(r, addr) \
    asm volatile("ldmatrix.sync.aligned.m8n8.x2.shared.b16 {%0,%1}, [%2];" \
        : "=r"((r)[0]), "=r"((r)[1]) : "r"(addr))

#define MMA_BF16(c, a, b) \
    asm volatile("mma.sync.aligned.m16n8k16.row.col.f32.bf16.bf16.f32 " \
        "{%0,%1,%2,%3}, {%4,%5,%6,%7}, {%8,%9}, {%0,%1,%2,%3};" \
        : "+f"((c)[0]), "+f"((c)[1]), "+f"((c)[2]), "+f"((c)[3]) \
        : "r"((a)[0]), "r"((a)[1]), "r"((a)[2]), "r"((a)[3]), \
          "r"((b)[0]), "r"((b)[1]))

#define CP_ASYNC16(dst, src, sz) \
    asm volatile("cp.async.cg.shared.global [%0], [%1], 16, %2;" \
        :: "r"(dst), "l"(src), "r"(sz))
#define CP_COMMIT()  asm volatile("cp.async.commit_group;" ::: "memory")
#define CP_WAIT1()   asm volatile("cp.async.wait_group 1;" ::: "memory")
#define CP_WAIT0()   asm volatile("cp.async.wait_group 0;" ::: "memory")

// ============================================================
// split: fp32 -> (hi bf16, lo bf16)
// ============================================================
__global__ void split_bf16_kernel(const float* __restrict__ s,
                                  __nv_bfloat16* __restrict__ hi,
                                  __nv_bfloat16* __restrict__ lo, int n)
{
    int i = blockIdx.x * blockDim.x + threadIdx.x;
    if (i >= n) return;
    float v = s[i];
    __nv_bfloat16 h = __float2bfloat16(v);
    hi[i] = h;
    lo[i] = __float2bfloat16(v - __bfloat162float(h));
}

// ============================================================
// bf16x3 GEMM via mma.sync (HMMA):
//   C[M,N] = (Ahi+Alo) @ (Bhi+Blo)^T, dropping Alo*Blo.
// A:[M,K], B:[N,K] row-major bf16; C fp32 row-major ld=N.
// CTA 128x128, Kc=32, 256 threads (8 warps, 4x2), warp tile 32x64.
// cp.async double-buffered; 80B-padded smem rows (conflict-free ldmatrix).
// grid: (ceil(N/128), M/128). M,K multiples of 128/32; N guarded (zfill).
// ============================================================
#define TILEB   10240      // 128 rows * 80B
#define STAGEB  40960      // 4 tiles
#define GSMEM   81920      // 2 stages

__global__ __launch_bounds__(256, 1)
void gemm_bf16x3_kernel(const __nv_bfloat16* __restrict__ Ahi_g,
                        const __nv_bfloat16* __restrict__ Alo_g,
                        const __nv_bfloat16* __restrict__ Bhi_g,
                        const __nv_bfloat16* __restrict__ Blo_g,
                        float* __restrict__ C, int N, int K)
{
    extern __shared__ char dsm[];
    const uint32_t sb = smem_u32(dsm);
    const int tid  = threadIdx.x;
    const int wid  = tid >> 5;
    const int lane = tid & 31;
    const int wm   = wid & 3;          // 0..3 -> 32-row slice
    const int wn   = wid >> 2;         // 0..1 -> 64-col slice
    const int m0 = blockIdx.y * 128;
    const int n0 = blockIdx.x * 128;

    // ---- async stage loader: 4 tiles x 128 rows x 32 bf16 ----
    auto stage_load = [&](int kc, int buf) {
        #pragma unroll
        for (int i = 0; i < 8; i++) {
            const int u   = tid + i * 256;
            const int t   = u >> 9;          // tile 0..3
            const int v   = u & 511;
            const int row = v >> 2;
            const int seg = v & 3;
            const uint32_t dst = sb + buf*STAGEB + t*TILEB + row*80 + seg*16;
            const __nv_bfloat16* src;
            int gr; int sz = 16;
            if (t < 2) { src = (t == 0) ? Ahi_g : Alo_g; gr = m0 + row; }
            else {
                src = (t == 2) ? Bhi_g : Blo_g; gr = n0 + row;
                if (gr >= N) { gr = 0; sz = 0; }
            }
            const void* g = src + (size_t)gr * K + kc*32 + seg*8;
            CP_ASYNC16(dst, g, sz);
        }
        CP_COMMIT();
    };

    float acc[2][8][4];
    #pragma unroll
    for (int mt = 0; mt < 2; mt++)
        #pragma unroll
        for (int nt = 0; nt < 8; nt++)
            #pragma unroll
            for (int q = 0; q < 4; q++) acc[mt][nt][q] = 0.f;

    const int nk = K >> 5;
    stage_load(0, 0);

    for (int kc = 0; kc < nk; kc++) {
        if (kc + 1 < nk) { stage_load(kc + 1, (kc + 1) & 1); CP_WAIT1(); }
        else             { CP_WAIT0(); }
        __syncthreads();

        const uint32_t base = sb + (kc & 1) * STAGEB;

        #pragma unroll
        for (int ks = 0; ks < 2; ks++) {
            uint32_t ah[2][4], al[2][4];
            #pragma unroll
            for (int mt = 0; mt < 2; mt++) {
                const uint32_t ra = base
                    + (wm*32 + mt*16 + (lane & 15)) * 80
                    + ks*32 + ((lane >> 4) & 1) * 16;
                LDSM4(ah[mt], ra);
                LDSM4(al[mt], ra + TILEB);
            }
            uint32_t bh[8][2], bl[8][2];
            #pragma unroll
            for (int nt = 0; nt < 8; nt++) {
                const uint32_t rb = base + 2*TILEB
                    + (wn*64 + nt*8 + (lane & 7)) * 80
                    + ks*32 + ((lane >> 3) & 1) * 16;
                LDSM2(bh[nt], rb);
                LDSM2(bl[nt], rb + TILEB);
            }
            #pragma unroll
            for (int mt = 0; mt < 2; mt++)
                #pragma unroll
                for (int nt = 0; nt < 8; nt++) {
                    MMA_BF16(acc[mt][nt], ah[mt], bh[nt]);
                    MMA_BF16(acc[mt][nt], ah[mt], bl[nt]);
                    MMA_BF16(acc[mt][nt], al[mt], bh[nt]);
                }
        }
        __syncthreads();
    }

    // ---- epilogue ----
    #pragma unroll
    for (int mt = 0; mt < 2; mt++) {
        const int r0 = m0 + wm*32 + mt*16 + (lane >> 2);
        #pragma unroll
        for (int nt = 0; nt < 8; nt++) {
            const int cc = n0 + wn*64 + nt*8 + (lane & 3)*2;
            if (cc < N) {
                *(float2*)(C + (size_t)r0       * N + cc) =
                    make_float2(acc[mt][nt][0], acc[mt][nt][1]);
                *(float2*)(C + (size_t)(r0 + 8) * N + cc) =
                    make_float2(acc[mt][nt][2], acc[mt][nt][3]);
            }
        }
    }
}

// ============================================================
// depthwise causal conv1d + bias + SiLU -> g_xssm
// ============================================================
__global__ void conv_silu_kernel(const float* __restrict__ cw,
                                 const float* __restrict__ cb)
{
    int idx = blockIdx.x * blockDim.x + threadIdx.x;
    if (idx >= BATCH * SEQLEN * DINNER) return;
    const int c = idx % DINNER;
    const int t = (idx / DINNER) % SEQLEN;
    const int b = idx / (DINNER * SEQLEN);

    const float* base = g_proj + (size_t)b * SEQLEN * DIP + DINNER + c;
    float acc = cb[c];
    #pragma unroll
    for (int j = 0; j < DCONV; j++) {
        const int ts = t - (DCONV - 1) + j;
        if (ts >= 0) acc = fmaf(cw[c*DCONV + j], base[(size_t)ts * DIP], acc);
    }
    g_xssm[idx] = acc / (1.f + expf(-acc));
}

// ============================================================
// dt path: dA = exp(softplus(dt_raw + dt_bias) * (-exp(A_log)))
// ============================================================
__global__ void dt_kernel(const float* __restrict__ A_log,
                          const float* __restrict__ dt_bias)
{
    int idx = blockIdx.x * blockDim.x + threadIdx.x;
    if (idx >= BATCH * SEQLEN * NHEADS) return;
    const int h = idx % NHEADS;
    const int row = idx / NHEADS;

    float dtr = g_proj[(size_t)row * DIP + 2*DINNER + 2*DSTATE + h] + dt_bias[h];
    float sp = (dtr > 20.f) ? dtr : log1pf(expf(dtr));
    float Aneg = -expf(A_log[h]);
    g_dA[idx] = expf(sp * Aneg);
}

// ============================================================
// Phase A: per-chunk local scan (zero init).
// ============================================================
__global__ __launch_bounds__(128, 1)
void scan_chunk_kernel()
{
    const int pg = blockIdx.x;
    const int h  = blockIdx.y;
    const int bz = blockIdx.z;
    const int b  = bz >> 5;
    const int c  = bz & 31;

    const int tid  = threadIdx.x;
    const int lane = tid & 31;
    const int w    = tid >> 5;
    const int pi   = lane & 3;
    const int ng   = lane >> 2;
    const int p_local = w*4 + pi;
    const int n0   = ng * 8;

    __shared__ float sB [64][64];
    __shared__ float sC [64][64];
    __shared__ float sX [64][16];
    __shared__ float sDA[64];
    __shared__ float sP [64];

    const size_t rowbase = (size_t)b * SEQLEN + (size_t)c * CHUNK;
    const int pcol = h*64 + pg*16;
    const size_t ci = ((size_t)(b*NHEADS + h) * NCHUNK + c);

    for (int u = tid; u < 64*16; u += 128) {
        const int r  = u >> 4;
        const int c4 = (u & 15) * 4;
        const float* src = g_proj + (rowbase + r) * (size_t)DIP;
        *(float4*)&sB[r][c4] = *(const float4*)(src + 2*DINNER + c4);
        *(float4*)&sC[r][c4] = *(const float4*)(src + 2*DINNER + DSTATE + c4);
    }
    for (int u = tid; u < 64*4; u += 128) {
        const int r  = u >> 2;
        const int c4 = (u & 3) * 4;
        *(float4*)&sX[r][c4] =
            *(const float4*)(g_xssm + (rowbase + r) * (size_t)DINNER + pcol + c4);
    }
    if (tid < 64) {
        float v = g_dA[(rowbase + tid) * NHEADS + h];
        sDA[tid] = v;
        sP[tid]  = v;
    }
    __syncthreads();

    #pragma unroll
    for (int off = 1; off < 64; off <<= 1) {
        float v = 0.f;
        if (tid < 64) {
            v = sP[tid];
            if (tid >= off) v *= sP[tid - off];
        }
        __syncthreads();
        if (tid < 64) sP[tid] = v;
        __syncthreads();
    }
    if (tid < 64 && pg == 0)
        g_P[ci*CHUNK + tid] = sP[tid];

    float s[8];
    #pragma unroll
    for (int j = 0; j < 8; j++) s[j] = 0.f;

    #pragma unroll 1
    for (int g = 0; g < 64; g += 8) {
        float acc[8];
        #pragma unroll
        for (int q = 0; q < 8; q++) {
            const int tt = g + q;
            const float da = sDA[tt];
            const float xv = sX[tt][p_local];
            float4 b0 = *(const float4*)&sB[tt][n0];
            float4 b1 = *(const float4*)&sB[tt][n0+4];
            float4 c0 = *(const float4*)&sC[tt][n0];
            float4 c1 = *(const float4*)&sC[tt][n0+4];
            s[0] = fmaf(da, s[0], b0.x * xv);
            s[1] = fmaf(da, s[1], b0.y * xv);
            s[2] = fmaf(da, s[2], b0.z * xv);
            s[3] = fmaf(da, s[3], b0.w * xv);
            s[4] = fmaf(da, s[4], b1.x * xv);
            s[5] = fmaf(da, s[5], b1.y * xv);
            s[6] = fmaf(da, s[6], b1.z * xv);
            s[7] = fmaf(da, s[7], b1.w * xv);
            float a0 = c0.x * s[0];
            float a1 = c0.y * s[1];
            a0 = fmaf(c0.z, s[2], a0);
            a1 = fmaf(c0.w, s[3], a1);
            a0 = fmaf(c1.x, s[4], a0);
            a1 = fmaf(c1.y, s[5], a1);
            a0 = fmaf(c1.z, s[6], a0);
            a1 = fmaf(c1.w, s[7], a1);
            acc[q] = a0 + a1;
        }
        #pragma unroll
        for (int q = 0; q < 8; q++) {
            float a = acc[q];
            a += __shfl_xor_sync(0xffffffffu, a, 4);
            a += __shfl_xor_sync(0xffffffffu, a, 8);
            a += __shfl_xor_sync(0xffffffffu, a, 16);
            acc[q] = a;
        }
        if (ng == 0) {
            #pragma unroll
            for (int q = 0; q < 8; q++) {
                g_y[(rowbase + g + q) * (size_t)DINNER + pcol + p_local] = acc[q];
            }
        }
    }

    float* vend = g_vend + ci * (size_t)(DSTATE*HEADDIM);
    #pragma unroll
    for (int j = 0; j < 8; j++)
        vend[(n0 + j) * HEADDIM + pg*16 + p_local] = s[j];
}

// ============================================================
// Phase B: carry propagation across chunks.
// ============================================================
__global__ __launch_bounds__(256, 1)
void carry_kernel()
{
    const int bh  = blockIdx.x;
    const int tid = threadIdx.x;

    float hreg[16];
    #pragma unroll
    for (int k = 0; k < 16; k++) hreg[k] = 0.f;

    for (int c = 0; c < NCHUNK; c++) {
        const size_t ci = (size_t)bh * NCHUNK + c;
        const float Pend = g_P[ci*CHUNK + (CHUNK-1)];
        float*       hs = g_hstart + ci * (size_t)(DSTATE*HEADDIM);
        const float* ve = g_vend   + ci * (size_t)(DSTATE*HEADDIM);
        #pragma unroll
        for (int k = 0; k < 16; k++) {
            const int cell = tid + k*256;
            hs[cell] = hreg[k];
            hreg[k] = fmaf(Pend, hreg[k], ve[cell]);
        }
    }
}

// ============================================================
// Phase C: correction + gate, writes y as bf16 hi/lo split.
// ============================================================
__global__ __launch_bounds__(256, 4)
void correct_gate_kernel()
{
    const int ci = blockIdx.x;
    const int c  = ci & 31;
    const int bh = ci >> 5;
    const int h  = bh & 15;
    const int b  = bh >> 4;
    const int tid = threadIdx.x;

    __shared__ float sCt[64][72];
    __shared__ float sHS[64][64];
    __shared__ float sPc[64];

    const size_t rowbase = (size_t)b * SEQLEN + (size_t)c * CHUNK;

    for (int u = tid; u < 64*16; u += 256) {
        const int r  = u >> 4;
        const int c4 = (u & 15) * 4;
        float4 v = *(const float4*)(g_proj + (rowbase + r) * (size_t)DIP
                                    + 2*DINNER + DSTATE + c4);
        sCt[c4+0][r] = v.x; sCt[c4+1][r] = v.y;
        sCt[c4+2][r] = v.z; sCt[c4+3][r] = v.w;
    }
    const float* hs = g_hstart + (size_t)ci * (DSTATE*HEADDIM);
    for (int u = tid; u < 64*16; u += 256) {
        const int r  = u >> 4;
        const int c4 = (u & 15) * 4;
        *(float4*)&sHS[r][c4] = *(const float4*)(hs + r*HEADDIM + c4);
    }
    if (tid < 64) sPc[tid] = g_P[(size_t)ci*CHUNK + tid];
    __syncthreads();

    const int tx = tid & 15;
    const int ty = tid >> 4;
    const int t0 = ty * 4;
    const int p0 = tx * 4;

    float acc[4][4];
    #pragma unroll
    for (int i = 0; i < 4; i++)
        #pragma unroll
        for (int j = 0; j < 4; j++) acc[i][j] = 0.f;

    #pragma unroll 4
    for (int n = 0; n < 64; n++) {
        float4 cv = *(const float4*)&sCt[n][t0];
        float4 hv = *(const float4*)&sHS[n][p0];
        float ct[4] = {cv.x, cv.y, cv.z, cv.w};
        float hh[4] = {hv.x, hv.y, hv.z, hv.w};
        #pragma unroll
        for (int i = 0; i < 4; i++)
            #pragma unroll
            for (int j = 0; j < 4; j++)
                acc[i][j] = fmaf(ct[i], hh[j], acc[i][j]);
    }

    #pragma unroll
    for (int i = 0; i < 4; i++) {
        const size_t row = rowbase + t0 + i;
        const float P = sPc[t0 + i];
        float4 yp = *(const float4*)(g_y + row * (size_t)DINNER + h*64 + p0);
        float4 zv = *(const float4*)(g_proj + row * (size_t)DIP + h*64 + p0);
        float ov[4];
        ov[0] = (yp.x + P*acc[i][0]) * (zv.x / (1.f + expf(-zv.x)));
        ov[1] = (yp.y + P*acc[i][1]) * (zv.y / (1.f + expf(-zv.y)));
        ov[2] = (yp.z + P*acc[i][2]) * (zv.z / (1.f + expf(-zv.z)));
        ov[3] = (yp.w + P*acc[i][3]) * (zv.w / (1.f + expf(-zv.w)));
        const size_t yo = row * (size_t)DINNER + h*64 + p0;
        #pragma unroll
        for (int j = 0; j < 4; j++) {
            __nv_bfloat16 hv = __float2bfloat16(ov[j]);
            g_yhi[yo + j] = hv;
            g_ylo[yo + j] = __float2bfloat16(ov[j] - __bfloat162float(hv));
        }
    }
}

// ============================================================
// launch
// ============================================================
extern "C" void kernel_launch(void* const* d_in, const int* in_sizes, int n_in,
                              void* d_out, int out_size)
{
    const float* x       = (const float*)d_in[0];
    const float* W_in    = (const float*)d_in[1];
    const float* conv_w  = (const float*)d_in[2];
    const float* conv_b  = (const float*)d_in[3];
    const float* A_log   = (const float*)d_in[4];
    const float* dt_bias = (const float*)d_in[5];
    const float* W_out   = (const float*)d_in[6];
    float* out = (float*)d_out;

    float* proj; cudaGetSymbolAddress((void**)&proj, g_proj);
    __nv_bfloat16 *xhi, *xlo, *wihi, *wilo, *wohi, *wolo, *yhi, *ylo;
    cudaGetSymbolAddress((void**)&xhi,  g_xhi);
    cudaGetSymbolAddress((void**)&xlo,  g_xlo);
    cudaGetSymbolAddress((void**)&wihi, g_wihi);
    cudaGetSymbolAddress((void**)&wilo, g_wilo);
    cudaGetSymbolAddress((void**)&wohi, g_wohi);
    cudaGetSymbolAddress((void**)&wolo, g_wolo);
    cudaGetSymbolAddress((void**)&yhi,  g_yhi);
    cudaGetSymbolAddress((void**)&ylo,  g_ylo);

    cudaFuncSetAttribute(gemm_bf16x3_kernel,
                         cudaFuncAttributeMaxDynamicSharedMemorySize, GSMEM);

    // 0) split inputs / weights into bf16 hi/lo
    {
        int n1 = MROWS * DMODEL;
        split_bf16_kernel<<<(n1 + 255)/256, 256>>>(x, xhi, xlo, n1);
        int n2 = DIP * DMODEL;
        split_bf16_kernel<<<(n2 + 255)/256, 256>>>(W_in, wihi, wilo, n2);
        int n3 = DMODEL * DINNER;
        split_bf16_kernel<<<(n3 + 255)/256, 256>>>(W_out, wohi, wolo, n3);
    }
    // 1) in_proj (HMMA): proj = x @ W_in^T   M=4096, N=2192, K=512
    {
        dim3 grid((DIP + 127)/128, MROWS/128);
        gemm_bf16x3_kernel<<<grid, 256, GSMEM>>>(xhi, xlo, wihi, wilo,
                                                 proj, DIP, DMODEL);
    }
    // 2) conv + silu
    {
        int total = BATCH*SEQLEN*DINNER;
        conv_silu_kernel<<<(total + 255)/256, 256>>>(conv_w, conv_b);
    }
    // 3) dt -> dA
    {
        int total = BATCH*SEQLEN*NHEADS;
        dt_kernel<<<(total + 255)/256, 256>>>(A_log, dt_bias);
    }
    // 4a) per-chunk local scan
    {
        dim3 grid(4, NHEADS, BATCH*NCHUNK);
        scan_chunk_kernel<<<grid, 128>>>();
    }
    // 4b) carry propagation
    carry_kernel<<<BATCH*NHEADS, 256>>>();
    // 4c) correction + gate (writes y hi/lo bf16)
    correct_gate_kernel<<<NCI, 256>>>();
    // 5) out_proj (HMMA): out = y @ W_out^T  M=4096, N=512, K=1024
    {
        dim3 grid(DMODEL/128, MROWS/128);
        gemm_bf16x3_kernel<<<grid, 256, GSMEM>>>(yhi, ylo, wohi, wolo,
                                                 out, DMODEL, DINNER);
    }
}